// round 1
// baseline (speedup 1.0000x reference)
#include <cuda_runtime.h>

typedef unsigned long long u64;

// ---------------- packed f32x2 helpers ----------------
__device__ __forceinline__ u64 pk2(float a, float b) {
    u64 r; asm("mov.b64 %0, {%1, %2};" : "=l"(r) : "f"(a), "f"(b)); return r;
}
__device__ __forceinline__ void unpk(u64 v, float& a, float& b) {
    asm("mov.b64 {%0, %1}, %2;" : "=f"(a), "=f"(b) : "l"(v));
}
__device__ __forceinline__ u64 ffma2(u64 a, u64 b, u64 c) {
    u64 d; asm("fma.rn.f32x2 %0, %1, %2, %3;" : "=l"(d) : "l"(a), "l"(b), "l"(c)); return d;
}
__device__ __forceinline__ u64 fadd2(u64 a, u64 b) {
    u64 d; asm("add.rn.f32x2 %0, %1, %2;" : "=l"(d) : "l"(a), "l"(b)); return d;
}
__device__ __forceinline__ u64 frelu2(u64 x) {
    float a, b; unpk(x, a, b);
    a = fmaxf(a, 0.f); b = fmaxf(b, 0.f);
    return pk2(a, b);
}

// ---------------- shared memory layout (u64 units, weights duplicated (w,w)) ----
#define OFF_A     0        // [128][4]  : W1[k][10..12] dup, pad
#define OFF_CE    512      // [4][128]  : b1+W1[:,0]+W1[:,6+e]
#define OFF_W2T   1024     // [128][40] : W2^T padded (col 39 = 0)
#define OFF_W3    6144     // [128][40] : W3 rows padded (col 39 = 0)
#define OFF_WMV   11264    // [128][16] : Wm^T | Wv^T interleaved per k
#define OFF_WD1   13312    // [32][20]  : Wd1[:,5..24]
#define OFF_WD2T  13952    // [32][12]  : Wd2^T
#define OFF_B2    14336    // [40]
#define OFF_B3    14376    // [128]
#define OFF_BM    14504    // [8]
#define OFF_BV    14512    // [8]
#define OFF_BD1   14520    // [32]      : bd1 + Wd1[:,0]
#define OFF_BD2   14552    // [12]
#define SMEM_U64  14564
#define SMEM_BYTES (SMEM_U64 * 8)

__device__ __forceinline__ void dupw(u64* s, int idx, float v) {
    float2 t; t.x = v; t.y = v;
    *reinterpret_cast<float2*>(s + idx) = t;
}

__global__ void __launch_bounds__(256)
vae_kernel(const float* __restrict__ initial_c,
           const float* __restrict__ current_c,
           const float* __restrict__ eps,
           const float* __restrict__ W1, const float* __restrict__ b1,
           const float* __restrict__ W2, const float* __restrict__ b2,
           const float* __restrict__ W3, const float* __restrict__ b3,
           const float* __restrict__ Wm, const float* __restrict__ bm,
           const float* __restrict__ Wv, const float* __restrict__ bv,
           const float* __restrict__ Wd1, const float* __restrict__ bd1,
           const float* __restrict__ Wd2, const float* __restrict__ bd2,
           float* __restrict__ out, int bsz)
{
    extern __shared__ __align__(16) u64 smu[];
    const int tid = threadIdx.x;

    // ---------- cooperative weight preprocessing ----------
    for (int k = tid; k < 128; k += 256) {
        dupw(smu, OFF_A + k * 4 + 0, W1[k * 13 + 10]);
        dupw(smu, OFF_A + k * 4 + 1, W1[k * 13 + 11]);
        dupw(smu, OFF_A + k * 4 + 2, W1[k * 13 + 12]);
        dupw(smu, OFF_A + k * 4 + 3, 0.f);
        dupw(smu, OFF_B3 + k, b3[k]);
        dupw(smu, OFF_W2T + k * 40 + 39, 0.f);
        dupw(smu, OFF_W3 + k * 40 + 39, 0.f);
    }
    for (int i = tid; i < 512; i += 256) {
        int e = i >> 7, k = i & 127;
        dupw(smu, OFF_CE + i, b1[k] + W1[k * 13 + 0] + W1[k * 13 + 6 + e]);
    }
    for (int i = tid; i < 39 * 128; i += 256) {
        int j = i >> 7, k = i & 127;
        dupw(smu, OFF_W2T + k * 40 + j, W2[i]);   // W2[j*128+k]
    }
    for (int i = tid; i < 128 * 39; i += 256) {
        int k = i / 39, j = i - k * 39;
        dupw(smu, OFF_W3 + k * 40 + j, W3[i]);    // W3[k*39+j]
    }
    for (int i = tid; i < 1024; i += 256) {
        int o = i >> 7, k = i & 127;
        dupw(smu, OFF_WMV + k * 16 + o, Wm[i]);       // Wm[o*128+k]
        dupw(smu, OFF_WMV + k * 16 + 8 + o, Wv[i]);
    }
    for (int i = tid; i < 640; i += 256) {
        int u = i / 20, t = i - u * 20;
        dupw(smu, OFF_WD1 + i, Wd1[u * 25 + 5 + t]);
    }
    for (int i = tid; i < 384; i += 256) {
        int u = i / 12, r = i - u * 12;
        dupw(smu, OFF_WD2T + i, Wd2[r * 32 + u]);
    }
    for (int i = tid; i < 40; i += 256) dupw(smu, OFF_B2 + i, (i < 39) ? b2[i] : 0.f);
    for (int i = tid; i < 8;  i += 256) { dupw(smu, OFF_BM + i, bm[i]); dupw(smu, OFF_BV + i, bv[i]); }
    for (int i = tid; i < 32; i += 256) dupw(smu, OFF_BD1 + i, bd1[i] + Wd1[i * 25 + 0]);
    for (int i = tid; i < 12; i += 256) dupw(smu, OFF_BD2 + i, bd2[i]);
    __syncthreads();

    // ---------- per-thread: 2 samples packed into f32x2 ----------
    const int r0 = blockIdx.x * 512 + tid;
    const int r1 = r0 + 256;

    const float* c0 = current_c + (size_t)r0 * 30;
    const float* c1 = current_c + (size_t)r1 * 30;

    // predicate triplets per edge: cols {e, 10+e, 14+4e}
    u64 pp[4][3];
#pragma unroll
    for (int e = 0; e < 4; e++) {
        pp[e][0] = pk2(c0[e],          c1[e]);
        pp[e][1] = pk2(c0[10 + e],     c1[10 + e]);
        pp[e][2] = pk2(c0[14 + 4 * e], c1[14 + 4 * e]);
    }

    // ---------- edge MLP: 13->128->39, relu, sum over 4 edges ----------
    u64 s40[40];
#pragma unroll
    for (int c = 0; c < 2; c++) {
        const int j0 = c * 20;
        u64 ss[20];
#pragma unroll
        for (int j = 0; j < 20; j++) ss[j] = 0ull;
#pragma unroll
        for (int e = 0; e < 4; e++) {
            u64 acc[20];
#pragma unroll
            for (int j = 0; j < 20; j++) acc[j] = 0ull;
            const u64* cerow = smu + OFF_CE + e * 128;
            const u64 p0 = pp[e][0], p1 = pp[e][1], p2 = pp[e][2];
#pragma unroll 4
            for (int k = 0; k < 128; k++) {
                const u64* arow = smu + OFF_A + k * 4;
                ulonglong2 a01 = *reinterpret_cast<const ulonglong2*>(arow);
                u64 a2 = arow[2];
                u64 h = cerow[k];
                h = ffma2(a01.x, p0, h);
                h = ffma2(a01.y, p1, h);
                h = ffma2(a2,    p2, h);
                h = frelu2(h);
                const ulonglong2* wr =
                    reinterpret_cast<const ulonglong2*>(smu + OFF_W2T + k * 40 + j0);
#pragma unroll
                for (int q = 0; q < 10; q++) {
                    ulonglong2 w = wr[q];
                    acc[2 * q]     = ffma2(h, w.x, acc[2 * q]);
                    acc[2 * q + 1] = ffma2(h, w.y, acc[2 * q + 1]);
                }
            }
#pragma unroll
            for (int j = 0; j < 20; j++)
                ss[j] = fadd2(ss[j], frelu2(fadd2(acc[j], smu[OFF_B2 + j0 + j])));
        }
#pragma unroll
        for (int j = 0; j < 20; j++) s40[j0 + j] = ss[j];
    }

    // ---------- trunk: 39->128 relu, then means / log_var (8 each) ----------
    u64 macc[8], vacc[8];
#pragma unroll
    for (int o = 0; o < 8; o++) { macc[o] = smu[OFF_BM + o]; vacc[o] = smu[OFF_BV + o]; }
#pragma unroll 2
    for (int k = 0; k < 128; k++) {
        u64 h = smu[OFF_B3 + k];
        const ulonglong2* wr = reinterpret_cast<const ulonglong2*>(smu + OFF_W3 + k * 40);
#pragma unroll
        for (int q = 0; q < 20; q++) {
            ulonglong2 w = wr[q];
            h = ffma2(s40[2 * q],     w.x, h);
            h = ffma2(s40[2 * q + 1], w.y, h);
        }
        h = frelu2(h);
        const ulonglong2* mv = reinterpret_cast<const ulonglong2*>(smu + OFF_WMV + k * 16);
#pragma unroll
        for (int q = 0; q < 4; q++) {
            ulonglong2 wm = mv[q], wv2 = mv[4 + q];
            macc[2 * q]     = ffma2(h, wm.x,  macc[2 * q]);
            macc[2 * q + 1] = ffma2(h, wm.y,  macc[2 * q + 1]);
            vacc[2 * q]     = ffma2(h, wv2.x, vacc[2 * q]);
            vacc[2 * q + 1] = ffma2(h, wv2.y, vacc[2 * q + 1]);
        }
    }

    // ---------- reparameterization + write means / log_var / z ----------
    float* om = out + (size_t)bsz * 12;
    float* ov = out + (size_t)bsz * 20;
    float* oz = out + (size_t)bsz * 28;
    u64 zq[8];
#pragma unroll
    for (int o = 0; o < 8; o++) {
        float m0, m1, v0, v1;
        unpk(macc[o], m0, m1);
        unpk(vacc[o], v0, v1);
        float e0 = eps[(size_t)r0 * 8 + o], e1 = eps[(size_t)r1 * 8 + o];
        float z0 = e0 * __expf(0.5f * v0) + m0;
        float z1 = e1 * __expf(0.5f * v1) + m1;
        om[(size_t)r0 * 8 + o] = m0;  om[(size_t)r1 * 8 + o] = m1;
        ov[(size_t)r0 * 8 + o] = v0;  ov[(size_t)r1 * 8 + o] = v1;
        oz[(size_t)r0 * 8 + o] = z0;  oz[(size_t)r1 * 8 + o] = z1;
        zq[o] = pk2(z0, z1);
    }

    // ---------- decoder: 20 (ic|z) -> 32 relu -> 12 sigmoid ----------
    const float* i0 = initial_c + (size_t)r0 * 30;
    const float* i1 = initial_c + (size_t)r1 * 30;
    u64 ic[12];
    {
        const int OID[12] = {0, 1, 2, 3, 10, 11, 12, 13, 14, 18, 22, 26};
#pragma unroll
        for (int t = 0; t < 12; t++) ic[t] = pk2(i0[OID[t]], i1[OID[t]]);
    }
    u64 d12[12];
#pragma unroll
    for (int r = 0; r < 12; r++) d12[r] = smu[OFF_BD2 + r];
#pragma unroll 4
    for (int u = 0; u < 32; u++) {
        u64 t = smu[OFF_BD1 + u];
        const ulonglong2* w = reinterpret_cast<const ulonglong2*>(smu + OFF_WD1 + u * 20);
#pragma unroll
        for (int q = 0; q < 6; q++) {
            ulonglong2 ww = w[q];
            t = ffma2(ic[2 * q],     ww.x, t);
            t = ffma2(ic[2 * q + 1], ww.y, t);
        }
#pragma unroll
        for (int q = 6; q < 10; q++) {
            ulonglong2 ww = w[q];
            t = ffma2(zq[2 * (q - 6)],     ww.x, t);
            t = ffma2(zq[2 * (q - 6) + 1], ww.y, t);
        }
        t = frelu2(t);
        const ulonglong2* w2 = reinterpret_cast<const ulonglong2*>(smu + OFF_WD2T + u * 12);
#pragma unroll
        for (int q = 0; q < 6; q++) {
            ulonglong2 ww = w2[q];
            d12[2 * q]     = ffma2(t, ww.x, d12[2 * q]);
            d12[2 * q + 1] = ffma2(t, ww.y, d12[2 * q + 1]);
        }
    }
#pragma unroll
    for (int r = 0; r < 12; r++) {
        float x0, x1; unpk(d12[r], x0, x1);
        out[(size_t)r0 * 12 + r] = 1.f / (1.f + __expf(-x0));
        out[(size_t)r1 * 12 + r] = 1.f / (1.f + __expf(-x1));
    }
}

extern "C" void kernel_launch(void* const* d_in, const int* in_sizes, int n_in,
                              void* d_out, int out_size) {
    const float* initial_c = (const float*)d_in[0];
    // d_in[1] = initial_s (unused by the reference computation)
    const float* current_c = (const float*)d_in[2];
    const float* eps       = (const float*)d_in[3];
    const float* W1  = (const float*)d_in[4];
    const float* b1  = (const float*)d_in[5];
    const float* W2  = (const float*)d_in[6];
    const float* b2  = (const float*)d_in[7];
    const float* W3  = (const float*)d_in[8];
    const float* b3  = (const float*)d_in[9];
    const float* Wm  = (const float*)d_in[10];
    const float* bm  = (const float*)d_in[11];
    const float* Wv  = (const float*)d_in[12];
    const float* bv  = (const float*)d_in[13];
    const float* Wd1 = (const float*)d_in[14];
    const float* bd1 = (const float*)d_in[15];
    const float* Wd2 = (const float*)d_in[16];
    const float* bd2 = (const float*)d_in[17];
    float* out = (float*)d_out;

    int bsz = in_sizes[3] / 8;           // eps is [B, 8]
    cudaFuncSetAttribute(vae_kernel, cudaFuncAttributeMaxDynamicSharedMemorySize, SMEM_BYTES);
    int blocks = bsz / 512;              // 2 samples/thread, 256 threads/block
    vae_kernel<<<blocks, 256, SMEM_BYTES>>>(
        initial_c, current_c, eps,
        W1, b1, W2, b2, W3, b3, Wm, bm, Wv, bv, Wd1, bd1, Wd2, bd2,
        out, bsz);
}

// round 3
// speedup vs baseline: 1.2561x; 1.2561x over previous
#include <cuda_runtime.h>

typedef unsigned long long u64;

// ---------------- packed f32x2 helpers ----------------
__device__ __forceinline__ u64 pk2(float a, float b) {
    u64 r; asm("mov.b64 %0, {%1, %2};" : "=l"(r) : "f"(a), "f"(b)); return r;
}
__device__ __forceinline__ void unpk(u64 v, float& a, float& b) {
    asm("mov.b64 {%0, %1}, %2;" : "=f"(a), "=f"(b) : "l"(v));
}
__device__ __forceinline__ u64 dup2(float a) {   // (a,a)
    u64 r; asm("mov.b64 %0, {%1, %1};" : "=l"(r) : "f"(a)); return r;
}
__device__ __forceinline__ u64 ffma2(u64 a, u64 b, u64 c) {
    u64 d; asm("fma.rn.f32x2 %0, %1, %2, %3;" : "=l"(d) : "l"(a), "l"(b), "l"(c)); return d;
}
__device__ __forceinline__ u64 fadd2(u64 a, u64 b) {
    u64 d; asm("add.rn.f32x2 %0, %1, %2;" : "=l"(d) : "l"(a), "l"(b)); return d;
}
__device__ __forceinline__ u64 frelu2(u64 x) {
    float a, b; unpk(x, a, b);
    a = fmaxf(a, 0.f); b = fmaxf(b, 0.f);
    return pk2(a, b);
}

// ---------------- shared memory layout ----------------
// u64 section (pre-duplicated (w,w) pairs):
#define OFF_ACE   0        // [4][128][4] u64 : {ce_e, W1[k][10], W1[k][11], W1[k][12]} dup
#define OFF_B2    2048     // [40]  dup
#define OFF_B3    2088     // [128] dup
#define OFF_BM    2216     // [8]   dup
#define OFF_BV    2224     // [8]   dup
#define OFF_BD1   2232     // [32]  dup : bd1 + Wd1[:,0]
#define OFF_BD2   2264     // [12]  dup
#define OFF_WD1   2276     // [32][20] u64 dup : Wd1[:,5..24]
#define OFF_WD2T  2916     // [32][12] u64 dup : Wd2^T
#define U64_END   3300
// float section (non-duplicated weights, 4 per LDS.128):
#define OFF_W2TF  6600     // [128][40] : W2^T padded (j=39 -> 0)
#define OFF_W3F   11720    // [128][40] : W3 rows padded
#define OFF_WMVF  16840    // [128][16] : Wm^T | Wv^T per k
#define FLT_END   18888
#define SMEM_BYTES (FLT_END * 4)   // 75552 B -> 2 CTAs/SM

__device__ __forceinline__ void dupw(u64* s, int idx, float v) {
    float2 t; t.x = v; t.y = v;
    *reinterpret_cast<float2*>(s + idx) = t;
}

__global__ void __launch_bounds__(256, 2)
vae_kernel(const float* __restrict__ initial_c,
           const float* __restrict__ current_c,
           const float* __restrict__ eps,
           const float* __restrict__ W1, const float* __restrict__ b1,
           const float* __restrict__ W2, const float* __restrict__ b2,
           const float* __restrict__ W3, const float* __restrict__ b3,
           const float* __restrict__ Wm, const float* __restrict__ bm,
           const float* __restrict__ Wv, const float* __restrict__ bv,
           const float* __restrict__ Wd1, const float* __restrict__ bd1,
           const float* __restrict__ Wd2, const float* __restrict__ bd2,
           float* __restrict__ out, int bsz)
{
    extern __shared__ __align__(16) u64 smu[];
    float* smf = reinterpret_cast<float*>(smu);
    const int tid = threadIdx.x;

    // ---------- cooperative weight preprocessing ----------
    for (int i = tid; i < 2048; i += 256) {       // ACE dup
        int e = i >> 9, k = (i >> 2) & 127, t = i & 3;
        float v;
        if (t == 0) v = b1[k] + W1[k * 13 + 0] + W1[k * 13 + 6 + e];
        else        v = W1[k * 13 + 9 + t];       // t=1..3 -> cols 10..12
        dupw(smu, OFF_ACE + i, v);
    }
    for (int i = tid; i < 5120; i += 256) {       // W2^T non-dup, padded
        int k = i / 40, j = i - k * 40;
        smf[OFF_W2TF + i] = (j < 39) ? W2[j * 128 + k] : 0.f;
    }
    for (int i = tid; i < 5120; i += 256) {       // W3 rows non-dup, padded
        int k = i / 40, j = i - k * 40;
        smf[OFF_W3F + i] = (j < 39) ? W3[k * 39 + j] : 0.f;
    }
    for (int i = tid; i < 2048; i += 256) {       // Wm^T | Wv^T non-dup
        int k = i >> 4, o = i & 15;
        smf[OFF_WMVF + i] = (o < 8) ? Wm[o * 128 + k] : Wv[(o - 8) * 128 + k];
    }
    for (int i = tid; i < 640; i += 256) {        // Wd1 dup (decoder, cheap)
        int u = i / 20, t = i - u * 20;
        dupw(smu, OFF_WD1 + i, Wd1[u * 25 + 5 + t]);
    }
    for (int i = tid; i < 384; i += 256) {        // Wd2^T dup
        int u = i / 12, r = i - u * 12;
        dupw(smu, OFF_WD2T + i, Wd2[r * 32 + u]);
    }
    for (int i = tid; i < 40; i += 256) dupw(smu, OFF_B2 + i, (i < 39) ? b2[i] : 0.f);
    for (int i = tid; i < 128; i += 256) dupw(smu, OFF_B3 + i, b3[i]);
    for (int i = tid; i < 8;  i += 256) { dupw(smu, OFF_BM + i, bm[i]); dupw(smu, OFF_BV + i, bv[i]); }
    for (int i = tid; i < 32; i += 256) dupw(smu, OFF_BD1 + i, bd1[i] + Wd1[i * 25 + 0]);
    for (int i = tid; i < 12; i += 256) dupw(smu, OFF_BD2 + i, bd2[i]);
    __syncthreads();

    // ---------- per-thread: 2 samples packed into f32x2 lanes ----------
    const int r0 = blockIdx.x * 512 + tid;
    const int r1 = r0 + 256;

    const float* c0 = current_c + (size_t)r0 * 30;
    const float* c1 = current_c + (size_t)r1 * 30;

    u64 pp[4][3];
#pragma unroll
    for (int e = 0; e < 4; e++) {
        pp[e][0] = pk2(c0[e],          c1[e]);
        pp[e][1] = pk2(c0[10 + e],     c1[10 + e]);
        pp[e][2] = pk2(c0[14 + 4 * e], c1[14 + 4 * e]);
    }

    // ---------- edge MLP: 13->128->39, relu, sum over 4 edges ----------
    u64 s40[40];
#pragma unroll 1
    for (int c2 = 0; c2 < 40; c2 += 20) {
        u64 ss[20];
#pragma unroll
        for (int j = 0; j < 20; j++) ss[j] = 0ull;
#pragma unroll 1
        for (int e = 0; e < 4; e++) {
            u64 acc[20];
#pragma unroll
            for (int j = 0; j < 20; j++) acc[j] = 0ull;
            const u64* ace = smu + OFF_ACE + e * 512;
            const u64 p0 = pp[e][0], p1 = pp[e][1], p2 = pp[e][2];
            const float* wbase = smf + OFF_W2TF + c2;
#pragma unroll 2
            for (int k = 0; k < 128; k++) {
                ulonglong2 t0 = *reinterpret_cast<const ulonglong2*>(ace + k * 4);
                ulonglong2 t1 = *reinterpret_cast<const ulonglong2*>(ace + k * 4 + 2);
                u64 h = t0.x;
                h = ffma2(t0.y, p0, h);
                h = ffma2(t1.x, p1, h);
                h = ffma2(t1.y, p2, h);
                h = frelu2(h);
                const float4* w4 = reinterpret_cast<const float4*>(wbase + k * 40);
#pragma unroll
                for (int q = 0; q < 5; q++) {
                    float4 w = w4[q];
                    acc[4 * q + 0] = ffma2(h, dup2(w.x), acc[4 * q + 0]);
                    acc[4 * q + 1] = ffma2(h, dup2(w.y), acc[4 * q + 1]);
                    acc[4 * q + 2] = ffma2(h, dup2(w.z), acc[4 * q + 2]);
                    acc[4 * q + 3] = ffma2(h, dup2(w.w), acc[4 * q + 3]);
                }
            }
#pragma unroll
            for (int j = 0; j < 20; j++)
                ss[j] = fadd2(ss[j], frelu2(fadd2(acc[j], smu[OFF_B2 + c2 + j])));
        }
#pragma unroll
        for (int j = 0; j < 20; j++) s40[c2 + j] = ss[j];
    }

    // ---------- trunk: 39->128 relu, then means / log_var (8 each) ----------
    u64 macc[8], vacc[8];
#pragma unroll
    for (int o = 0; o < 8; o++) { macc[o] = smu[OFF_BM + o]; vacc[o] = smu[OFF_BV + o]; }
#pragma unroll 2
    for (int k = 0; k < 128; k++) {
        const float4* w3 = reinterpret_cast<const float4*>(smf + OFF_W3F + k * 40);
        u64 h0 = 0ull, h1 = 0ull, h2 = 0ull, h3 = 0ull;
#pragma unroll
        for (int q = 0; q < 10; q++) {            // 10 float4 = all 40 cols (fix!)
            float4 w = w3[q];
            h0 = ffma2(s40[4 * q + 0], dup2(w.x), h0);
            h1 = ffma2(s40[4 * q + 1], dup2(w.y), h1);
            h2 = ffma2(s40[4 * q + 2], dup2(w.z), h2);
            h3 = ffma2(s40[4 * q + 3], dup2(w.w), h3);
        }
        u64 h = fadd2(fadd2(h0, h1), fadd2(h2, h3));
        h = fadd2(h, smu[OFF_B3 + k]);
        h = frelu2(h);
        const float4* wmv = reinterpret_cast<const float4*>(smf + OFF_WMVF + k * 16);
        float4 m0 = wmv[0], m1 = wmv[1], v0 = wmv[2], v1 = wmv[3];
        macc[0] = ffma2(h, dup2(m0.x), macc[0]);
        macc[1] = ffma2(h, dup2(m0.y), macc[1]);
        macc[2] = ffma2(h, dup2(m0.z), macc[2]);
        macc[3] = ffma2(h, dup2(m0.w), macc[3]);
        macc[4] = ffma2(h, dup2(m1.x), macc[4]);
        macc[5] = ffma2(h, dup2(m1.y), macc[5]);
        macc[6] = ffma2(h, dup2(m1.z), macc[6]);
        macc[7] = ffma2(h, dup2(m1.w), macc[7]);
        vacc[0] = ffma2(h, dup2(v0.x), vacc[0]);
        vacc[1] = ffma2(h, dup2(v0.y), vacc[1]);
        vacc[2] = ffma2(h, dup2(v0.z), vacc[2]);
        vacc[3] = ffma2(h, dup2(v0.w), vacc[3]);
        vacc[4] = ffma2(h, dup2(v1.x), vacc[4]);
        vacc[5] = ffma2(h, dup2(v1.y), vacc[5]);
        vacc[6] = ffma2(h, dup2(v1.z), vacc[6]);
        vacc[7] = ffma2(h, dup2(v1.w), vacc[7]);
    }

    // ---------- reparameterization + write means / log_var / z ----------
    float* om = out + (size_t)bsz * 12;
    float* ov = out + (size_t)bsz * 20;
    float* oz = out + (size_t)bsz * 28;
    u64 zq[8];
#pragma unroll
    for (int o = 0; o < 8; o++) {
        float m0, m1, v0, v1;
        unpk(macc[o], m0, m1);
        unpk(vacc[o], v0, v1);
        float e0 = eps[(size_t)r0 * 8 + o], e1 = eps[(size_t)r1 * 8 + o];
        float z0 = e0 * __expf(0.5f * v0) + m0;
        float z1 = e1 * __expf(0.5f * v1) + m1;
        om[(size_t)r0 * 8 + o] = m0;  om[(size_t)r1 * 8 + o] = m1;
        ov[(size_t)r0 * 8 + o] = v0;  ov[(size_t)r1 * 8 + o] = v1;
        oz[(size_t)r0 * 8 + o] = z0;  oz[(size_t)r1 * 8 + o] = z1;
        zq[o] = pk2(z0, z1);
    }

    // ---------- decoder: 20 (ic|z) -> 32 relu -> 12 sigmoid ----------
    const float* i0 = initial_c + (size_t)r0 * 30;
    const float* i1 = initial_c + (size_t)r1 * 30;
    u64 ic[12];
    {
        const int OID[12] = {0, 1, 2, 3, 10, 11, 12, 13, 14, 18, 22, 26};
#pragma unroll
        for (int t = 0; t < 12; t++) ic[t] = pk2(i0[OID[t]], i1[OID[t]]);
    }
    u64 d12[12];
#pragma unroll
    for (int r = 0; r < 12; r++) d12[r] = smu[OFF_BD2 + r];
#pragma unroll 4
    for (int u = 0; u < 32; u++) {
        u64 t = smu[OFF_BD1 + u];
        const ulonglong2* w = reinterpret_cast<const ulonglong2*>(smu + OFF_WD1 + u * 20);
#pragma unroll
        for (int q = 0; q < 6; q++) {
            ulonglong2 ww = w[q];
            t = ffma2(ic[2 * q],     ww.x, t);
            t = ffma2(ic[2 * q + 1], ww.y, t);
        }
#pragma unroll
        for (int q = 6; q < 10; q++) {
            ulonglong2 ww = w[q];
            t = ffma2(zq[2 * (q - 6)],     ww.x, t);
            t = ffma2(zq[2 * (q - 6) + 1], ww.y, t);
        }
        t = frelu2(t);
        const ulonglong2* w2 = reinterpret_cast<const ulonglong2*>(smu + OFF_WD2T + u * 12);
#pragma unroll
        for (int q = 0; q < 6; q++) {
            ulonglong2 ww = w2[q];
            d12[2 * q]     = ffma2(t, ww.x, d12[2 * q]);
            d12[2 * q + 1] = ffma2(t, ww.y, d12[2 * q + 1]);
        }
    }
#pragma unroll
    for (int r = 0; r < 12; r++) {
        float x0, x1; unpk(d12[r], x0, x1);
        out[(size_t)r0 * 12 + r] = 1.f / (1.f + __expf(-x0));
        out[(size_t)r1 * 12 + r] = 1.f / (1.f + __expf(-x1));
    }
}

extern "C" void kernel_launch(void* const* d_in, const int* in_sizes, int n_in,
                              void* d_out, int out_size) {
    const float* initial_c = (const float*)d_in[0];
    // d_in[1] = initial_s (unused by the reference computation)
    const float* current_c = (const float*)d_in[2];
    const float* eps       = (const float*)d_in[3];
    const float* W1  = (const float*)d_in[4];
    const float* b1  = (const float*)d_in[5];
    const float* W2  = (const float*)d_in[6];
    const float* b2  = (const float*)d_in[7];
    const float* W3  = (const float*)d_in[8];
    const float* b3  = (const float*)d_in[9];
    const float* Wm  = (const float*)d_in[10];
    const float* bm  = (const float*)d_in[11];
    const float* Wv  = (const float*)d_in[12];
    const float* bv  = (const float*)d_in[13];
    const float* Wd1 = (const float*)d_in[14];
    const float* bd1 = (const float*)d_in[15];
    const float* Wd2 = (const float*)d_in[16];
    const float* bd2 = (const float*)d_in[17];
    float* out = (float*)d_out;

    int bsz = in_sizes[3] / 8;           // eps is [B, 8]
    cudaFuncSetAttribute(vae_kernel, cudaFuncAttributeMaxDynamicSharedMemorySize, SMEM_BYTES);
    int blocks = bsz / 512;              // 2 samples/thread, 256 threads/block
    vae_kernel<<<blocks, 256, SMEM_BYTES>>>(
        initial_c, current_c, eps,
        W1, b1, W2, b2, W3, b3, Wm, bm, Wv, bv, Wd1, bd1, Wd2, bd2,
        out, bsz);
}

// round 4
// speedup vs baseline: 1.3676x; 1.0888x over previous
#include <cuda_runtime.h>

typedef unsigned long long u64;

// ---------------- packed f32x2 helpers ----------------
__device__ __forceinline__ u64 pk2(float a, float b) {
    u64 r; asm("mov.b64 %0, {%1, %2};" : "=l"(r) : "f"(a), "f"(b)); return r;
}
__device__ __forceinline__ void unpk(u64 v, float& a, float& b) {
    asm("mov.b64 {%0, %1}, %2;" : "=f"(a), "=f"(b) : "l"(v));
}
__device__ __forceinline__ u64 dup2(float a) {   // (a,a)
    u64 r; asm("mov.b64 %0, {%1, %1};" : "=l"(r) : "f"(a)); return r;
}
__device__ __forceinline__ u64 ffma2(u64 a, u64 b, u64 c) {
    u64 d; asm("fma.rn.f32x2 %0, %1, %2, %3;" : "=l"(d) : "l"(a), "l"(b), "l"(c)); return d;
}
__device__ __forceinline__ u64 fadd2(u64 a, u64 b) {
    u64 d; asm("add.rn.f32x2 %0, %1, %2;" : "=l"(d) : "l"(a), "l"(b)); return d;
}
__device__ __forceinline__ u64 frelu2(u64 x) {
    float a, b; unpk(x, a, b);
    a = fmaxf(a, 0.f); b = fmaxf(b, 0.f);
    return pk2(a, b);
}

// ---------------- shared memory layout (u64 units) ----------------
#define OFF_ACE   0        // [4][128][4] dup : {ce_e, W1[k][10], W1[k][11], W1[k][12]}
#define OFF_W2TP  2048     // [128][20] f32x2 j-pairs of W2^T row (j=39 padded 0)
#define OFF_W3P   4608     // [128][20] f32x2 j-pairs of W3 row  (j=39 padded 0)
#define OFF_WMVP  7168     // [128][8]  f32x2 o-pairs: 4x Wm | 4x Wv
#define OFF_B2P   8192     // [20] f32x2 j-pairs of b2
#define OFF_B3    8212     // [128] dup
#define OFF_BMP   8340     // [4] f32x2 o-pairs of bm
#define OFF_BVP   8344     // [4] f32x2 o-pairs of bv
#define OFF_BD1   8348     // [32] dup : bd1 + Wd1[:,0]
#define OFF_BD2   8380     // [12] dup
#define OFF_WD1   8392     // [32][20] dup : Wd1[:,5..24]
#define OFF_WD2T  9032     // [32][12] dup : Wd2^T
#define SMEM_U64  9416
#define SMEM_BYTES (SMEM_U64 * 8)   // 75328 B -> 2 CTAs/SM

__device__ __forceinline__ void dupw(u64* s, int idx, float v) {
    float2 t; t.x = v; t.y = v;
    *reinterpret_cast<float2*>(s + idx) = t;
}
__device__ __forceinline__ void st2(u64* s, int idx, float a, float b) {
    float2 t; t.x = a; t.y = b;
    *reinterpret_cast<float2*>(s + idx) = t;
}

__global__ void __launch_bounds__(256, 2)
vae_kernel(const float* __restrict__ initial_c,
           const float* __restrict__ current_c,
           const float* __restrict__ eps,
           const float* __restrict__ W1, const float* __restrict__ b1,
           const float* __restrict__ W2, const float* __restrict__ b2,
           const float* __restrict__ W3, const float* __restrict__ b3,
           const float* __restrict__ Wm, const float* __restrict__ bm,
           const float* __restrict__ Wv, const float* __restrict__ bv,
           const float* __restrict__ Wd1, const float* __restrict__ bd1,
           const float* __restrict__ Wd2, const float* __restrict__ bd2,
           float* __restrict__ out, int bsz)
{
    extern __shared__ __align__(16) u64 smu[];
    const int tid = threadIdx.x;

    // ---------- cooperative weight preprocessing ----------
    for (int i = tid; i < 2048; i += 256) {       // ACE dup
        int e = i >> 9, k = (i >> 2) & 127, t = i & 3;
        float v;
        if (t == 0) v = b1[k] + W1[k * 13 + 0] + W1[k * 13 + 6 + e];
        else        v = W1[k * 13 + 9 + t];       // t=1..3 -> cols 10..12
        dupw(smu, OFF_ACE + i, v);
    }
    for (int i = tid; i < 2560; i += 256) {       // W2^T j-pairs
        int k = i / 20, jp = i - k * 20;
        int j0 = 2 * jp, j1 = 2 * jp + 1;
        st2(smu, OFF_W2TP + i,
            (j0 < 39) ? W2[j0 * 128 + k] : 0.f,
            (j1 < 39) ? W2[j1 * 128 + k] : 0.f);
    }
    for (int i = tid; i < 2560; i += 256) {       // W3 row j-pairs
        int k = i / 20, jp = i - k * 20;
        int j0 = 2 * jp, j1 = 2 * jp + 1;
        st2(smu, OFF_W3P + i,
            (j0 < 39) ? W3[k * 39 + j0] : 0.f,
            (j1 < 39) ? W3[k * 39 + j1] : 0.f);
    }
    for (int i = tid; i < 1024; i += 256) {       // Wm|Wv o-pairs
        int k = i >> 3, q = i & 7;
        float a, b;
        if (q < 4) { a = Wm[(2 * q) * 128 + k];       b = Wm[(2 * q + 1) * 128 + k]; }
        else       { a = Wv[(2 * (q - 4)) * 128 + k]; b = Wv[(2 * (q - 4) + 1) * 128 + k]; }
        st2(smu, OFF_WMVP + i, a, b);
    }
    for (int i = tid; i < 20; i += 256)
        st2(smu, OFF_B2P + i, b2[2 * i], (2 * i + 1 < 39) ? b2[2 * i + 1] : 0.f);
    for (int i = tid; i < 128; i += 256) dupw(smu, OFF_B3 + i, b3[i]);
    for (int i = tid; i < 4; i += 256) {
        st2(smu, OFF_BMP + i, bm[2 * i], bm[2 * i + 1]);
        st2(smu, OFF_BVP + i, bv[2 * i], bv[2 * i + 1]);
    }
    for (int i = tid; i < 640; i += 256) {        // Wd1 dup
        int u = i / 20, t = i - u * 20;
        dupw(smu, OFF_WD1 + i, Wd1[u * 25 + 5 + t]);
    }
    for (int i = tid; i < 384; i += 256) {        // Wd2^T dup
        int u = i / 12, r = i - u * 12;
        dupw(smu, OFF_WD2T + i, Wd2[r * 32 + u]);
    }
    for (int i = tid; i < 32; i += 256) dupw(smu, OFF_BD1 + i, bd1[i] + Wd1[i * 25 + 0]);
    for (int i = tid; i < 12; i += 256) dupw(smu, OFF_BD2 + i, bd2[i]);
    __syncthreads();

    // ---------- per-thread: 2 samples; accumulators hold (j,j+1) pairs per sample ----------
    const int r0 = blockIdx.x * 512 + tid;
    const int r1 = r0 + 256;

    const float* c0 = current_c + (size_t)r0 * 30;
    const float* c1 = current_c + (size_t)r1 * 30;

    // s40x[jp] = (sum_j, sum_j+1) for sample x, jp = 0..19
    u64 s400[20], s401[20];

#pragma unroll 1
    for (int c = 0; c < 2; c++) {                 // j-pair chunks: jp in [10c, 10c+10)
        u64 ss0[10], ss1[10];
#pragma unroll
        for (int q = 0; q < 10; q++) { ss0[q] = 0ull; ss1[q] = 0ull; }
#pragma unroll 1
        for (int e = 0; e < 4; e++) {
            const u64 p0 = pk2(c0[e],          c1[e]);
            const u64 p1 = pk2(c0[10 + e],     c1[10 + e]);
            const u64 p2 = pk2(c0[14 + 4 * e], c1[14 + 4 * e]);
            u64 a0[10], a1[10];
#pragma unroll
            for (int q = 0; q < 10; q++) { a0[q] = 0ull; a1[q] = 0ull; }
            const u64* ace = smu + OFF_ACE + e * 512;
            const u64* wrow = smu + OFF_W2TP + c * 10;
#pragma unroll 2
            for (int k = 0; k < 128; k++) {
                ulonglong2 t0 = *reinterpret_cast<const ulonglong2*>(ace + k * 4);
                ulonglong2 t1 = *reinterpret_cast<const ulonglong2*>(ace + k * 4 + 2);
                u64 h = t0.x;
                h = ffma2(t0.y, p0, h);
                h = ffma2(t1.x, p1, h);
                h = ffma2(t1.y, p2, h);
                h = frelu2(h);
                float hl, hh; unpk(h, hl, hh);
                u64 H0 = dup2(hl), H1 = dup2(hh);
                const ulonglong2* w = reinterpret_cast<const ulonglong2*>(wrow + k * 20);
#pragma unroll
                for (int q = 0; q < 5; q++) {
                    ulonglong2 ww = w[q];
                    a0[2 * q]     = ffma2(H0, ww.x, a0[2 * q]);
                    a0[2 * q + 1] = ffma2(H0, ww.y, a0[2 * q + 1]);
                    a1[2 * q]     = ffma2(H1, ww.x, a1[2 * q]);
                    a1[2 * q + 1] = ffma2(H1, ww.y, a1[2 * q + 1]);
                }
            }
#pragma unroll
            for (int q = 0; q < 10; q++) {
                u64 b = smu[OFF_B2P + c * 10 + q];
                ss0[q] = fadd2(ss0[q], frelu2(fadd2(a0[q], b)));
                ss1[q] = fadd2(ss1[q], frelu2(fadd2(a1[q], b)));
            }
        }
#pragma unroll
        for (int q = 0; q < 10; q++) { s400[c * 10 + q] = ss0[q]; s401[c * 10 + q] = ss1[q]; }
    }

    // ---------- trunk: 39->128 relu, then means / log_var ----------
    // head accumulators: o-pairs per sample
    u64 mc0[4], mc1[4], vc0[4], vc1[4];
#pragma unroll
    for (int q = 0; q < 4; q++) {
        mc0[q] = smu[OFF_BMP + q]; mc1[q] = mc0[q];
        vc0[q] = smu[OFF_BVP + q]; vc1[q] = vc0[q];
    }
#pragma unroll 2
    for (int k = 0; k < 128; k++) {
        const ulonglong2* w3 = reinterpret_cast<const ulonglong2*>(smu + OFF_W3P + k * 20);
        u64 c0a = 0ull, c0b = 0ull, c1a = 0ull, c1b = 0ull;
#pragma unroll
        for (int q = 0; q < 10; q++) {
            ulonglong2 ww = w3[q];
            c0a = ffma2(s400[2 * q],     ww.x, c0a);
            c0b = ffma2(s400[2 * q + 1], ww.y, c0b);
            c1a = ffma2(s401[2 * q],     ww.x, c1a);
            c1b = ffma2(s401[2 * q + 1], ww.y, c1b);
        }
        u64 t0 = fadd2(c0a, c0b), t1 = fadd2(c1a, c1b);
        float x0, y0, x1, y1;
        unpk(t0, x0, y0); unpk(t1, x1, y1);
        u64 h = pk2(x0 + y0, x1 + y1);            // (h_s0, h_s1)
        h = fadd2(h, smu[OFF_B3 + k]);
        h = frelu2(h);
        float h0, h1; unpk(h, h0, h1);
        u64 H0 = dup2(h0), H1 = dup2(h1);
        const ulonglong2* wmv = reinterpret_cast<const ulonglong2*>(smu + OFF_WMVP + k * 8);
        ulonglong2 wa = wmv[0], wb = wmv[1], wc = wmv[2], wd = wmv[3];
        mc0[0] = ffma2(H0, wa.x, mc0[0]);
        mc0[1] = ffma2(H0, wa.y, mc0[1]);
        mc0[2] = ffma2(H0, wb.x, mc0[2]);
        mc0[3] = ffma2(H0, wb.y, mc0[3]);
        mc1[0] = ffma2(H1, wa.x, mc1[0]);
        mc1[1] = ffma2(H1, wa.y, mc1[1]);
        mc1[2] = ffma2(H1, wb.x, mc1[2]);
        mc1[3] = ffma2(H1, wb.y, mc1[3]);
        vc0[0] = ffma2(H0, wc.x, vc0[0]);
        vc0[1] = ffma2(H0, wc.y, vc0[1]);
        vc0[2] = ffma2(H0, wd.x, vc0[2]);
        vc0[3] = ffma2(H0, wd.y, vc0[3]);
        vc1[0] = ffma2(H1, wc.x, vc1[0]);
        vc1[1] = ffma2(H1, wc.y, vc1[1]);
        vc1[2] = ffma2(H1, wd.x, vc1[2]);
        vc1[3] = ffma2(H1, wd.y, vc1[3]);
    }

    // ---------- reparameterization + vectorized writes ----------
    float me0[8], me1[8], lv0[8], lv1[8];
#pragma unroll
    for (int q = 0; q < 4; q++) {
        unpk(mc0[q], me0[2 * q], me0[2 * q + 1]);
        unpk(mc1[q], me1[2 * q], me1[2 * q + 1]);
        unpk(vc0[q], lv0[2 * q], lv0[2 * q + 1]);
        unpk(vc1[q], lv1[2 * q], lv1[2 * q + 1]);
    }
    const float4* e40 = reinterpret_cast<const float4*>(eps + (size_t)r0 * 8);
    const float4* e41 = reinterpret_cast<const float4*>(eps + (size_t)r1 * 8);
    float4 ea0 = e40[0], eb0 = e40[1], ea1 = e41[0], eb1 = e41[1];
    float ep0[8] = {ea0.x, ea0.y, ea0.z, ea0.w, eb0.x, eb0.y, eb0.z, eb0.w};
    float ep1[8] = {ea1.x, ea1.y, ea1.z, ea1.w, eb1.x, eb1.y, eb1.z, eb1.w};
    float z0[8], z1[8];
    u64 zq[8];
#pragma unroll
    for (int o = 0; o < 8; o++) {
        z0[o] = ep0[o] * __expf(0.5f * lv0[o]) + me0[o];
        z1[o] = ep1[o] * __expf(0.5f * lv1[o]) + me1[o];
        zq[o] = pk2(z0[o], z1[o]);
    }
    {
        float4* om0 = reinterpret_cast<float4*>(out + (size_t)bsz * 12 + (size_t)r0 * 8);
        float4* om1 = reinterpret_cast<float4*>(out + (size_t)bsz * 12 + (size_t)r1 * 8);
        float4* ov0 = reinterpret_cast<float4*>(out + (size_t)bsz * 20 + (size_t)r0 * 8);
        float4* ov1 = reinterpret_cast<float4*>(out + (size_t)bsz * 20 + (size_t)r1 * 8);
        float4* oz0 = reinterpret_cast<float4*>(out + (size_t)bsz * 28 + (size_t)r0 * 8);
        float4* oz1 = reinterpret_cast<float4*>(out + (size_t)bsz * 28 + (size_t)r1 * 8);
        om0[0] = make_float4(me0[0], me0[1], me0[2], me0[3]);
        om0[1] = make_float4(me0[4], me0[5], me0[6], me0[7]);
        om1[0] = make_float4(me1[0], me1[1], me1[2], me1[3]);
        om1[1] = make_float4(me1[4], me1[5], me1[6], me1[7]);
        ov0[0] = make_float4(lv0[0], lv0[1], lv0[2], lv0[3]);
        ov0[1] = make_float4(lv0[4], lv0[5], lv0[6], lv0[7]);
        ov1[0] = make_float4(lv1[0], lv1[1], lv1[2], lv1[3]);
        ov1[1] = make_float4(lv1[4], lv1[5], lv1[6], lv1[7]);
        oz0[0] = make_float4(z0[0], z0[1], z0[2], z0[3]);
        oz0[1] = make_float4(z0[4], z0[5], z0[6], z0[7]);
        oz1[0] = make_float4(z1[0], z1[1], z1[2], z1[3]);
        oz1[1] = make_float4(z1[4], z1[5], z1[6], z1[7]);
    }

    // ---------- decoder: 20 (ic|z) -> 32 relu -> 12 sigmoid ----------
    const float* i0 = initial_c + (size_t)r0 * 30;
    const float* i1 = initial_c + (size_t)r1 * 30;
    u64 ic[12];
    {
        const int OID[12] = {0, 1, 2, 3, 10, 11, 12, 13, 14, 18, 22, 26};
#pragma unroll
        for (int t = 0; t < 12; t++) ic[t] = pk2(i0[OID[t]], i1[OID[t]]);
    }
    u64 d12[12];
#pragma unroll
    for (int r = 0; r < 12; r++) d12[r] = smu[OFF_BD2 + r];
#pragma unroll 4
    for (int u = 0; u < 32; u++) {
        u64 t = smu[OFF_BD1 + u];
        const ulonglong2* w = reinterpret_cast<const ulonglong2*>(smu + OFF_WD1 + u * 20);
#pragma unroll
        for (int q = 0; q < 6; q++) {
            ulonglong2 ww = w[q];
            t = ffma2(ic[2 * q],     ww.x, t);
            t = ffma2(ic[2 * q + 1], ww.y, t);
        }
#pragma unroll
        for (int q = 6; q < 10; q++) {
            ulonglong2 ww = w[q];
            t = ffma2(zq[2 * (q - 6)],     ww.x, t);
            t = ffma2(zq[2 * (q - 6) + 1], ww.y, t);
        }
        t = frelu2(t);
        const ulonglong2* w2 = reinterpret_cast<const ulonglong2*>(smu + OFF_WD2T + u * 12);
#pragma unroll
        for (int q = 0; q < 6; q++) {
            ulonglong2 ww = w2[q];
            d12[2 * q]     = ffma2(t, ww.x, d12[2 * q]);
            d12[2 * q + 1] = ffma2(t, ww.y, d12[2 * q + 1]);
        }
    }
    {
        float o0[12], o1[12];
#pragma unroll
        for (int r = 0; r < 12; r++) {
            float x0, x1; unpk(d12[r], x0, x1);
            o0[r] = 1.f / (1.f + __expf(-x0));
            o1[r] = 1.f / (1.f + __expf(-x1));
        }
        float4* p0 = reinterpret_cast<float4*>(out + (size_t)r0 * 12);
        float4* p1 = reinterpret_cast<float4*>(out + (size_t)r1 * 12);
        p0[0] = make_float4(o0[0], o0[1], o0[2],  o0[3]);
        p0[1] = make_float4(o0[4], o0[5], o0[6],  o0[7]);
        p0[2] = make_float4(o0[8], o0[9], o0[10], o0[11]);
        p1[0] = make_float4(o1[0], o1[1], o1[2],  o1[3]);
        p1[1] = make_float4(o1[4], o1[5], o1[6],  o1[7]);
        p1[2] = make_float4(o1[8], o1[9], o1[10], o1[11]);
    }
}

extern "C" void kernel_launch(void* const* d_in, const int* in_sizes, int n_in,
                              void* d_out, int out_size) {
    const float* initial_c = (const float*)d_in[0];
    // d_in[1] = initial_s (unused by the reference computation)
    const float* current_c = (const float*)d_in[2];
    const float* eps       = (const float*)d_in[3];
    const float* W1  = (const float*)d_in[4];
    const float* b1  = (const float*)d_in[5];
    const float* W2  = (const float*)d_in[6];
    const float* b2  = (const float*)d_in[7];
    const float* W3  = (const float*)d_in[8];
    const float* b3  = (const float*)d_in[9];
    const float* Wm  = (const float*)d_in[10];
    const float* bm  = (const float*)d_in[11];
    const float* Wv  = (const float*)d_in[12];
    const float* bv  = (const float*)d_in[13];
    const float* Wd1 = (const float*)d_in[14];
    const float* bd1 = (const float*)d_in[15];
    const float* Wd2 = (const float*)d_in[16];
    const float* bd2 = (const float*)d_in[17];
    float* out = (float*)d_out;

    int bsz = in_sizes[3] / 8;           // eps is [B, 8]
    cudaFuncSetAttribute(vae_kernel, cudaFuncAttributeMaxDynamicSharedMemorySize, SMEM_BYTES);
    int blocks = bsz / 512;              // 2 samples/thread, 256 threads/block
    vae_kernel<<<blocks, 256, SMEM_BYTES>>>(
        initial_c, current_c, eps,
        W1, b1, W2, b2, W3, b3, Wm, bm, Wv, bv, Wd1, bd1, Wd2, bd2,
        out, bsz);
}